// round 13
// baseline (speedup 1.0000x reference)
#include <cuda_runtime.h>
#include <cuda_bf16.h>

#define N_NODES 100000
#define N_EDGES 1600000
#define NB_SCAN 98            // ceil(100000/1024)
// layer dims: F_IN=128, HID=64, N_CLS=40

// Scratch (device globals: allocation-free, graph-safe)
__device__ __align__(16) __nv_bfloat16 g_y1l[N_NODES * 64];  // x@W1_l, bf16 (gathered table)
__device__ __align__(16) float g_y1r[N_NODES * 64];          // x@W1_r, fp32 (self part)
__device__ __align__(16) float g_h[N_NODES * 64];            // relu output
__device__ __align__(16) float g_y2[N_NODES * 80];           // [h@W2_l | h@W2_r]
__device__ int g_deg[N_NODES];        // in-degree histogram
__device__ int g_excl[N_NODES];       // block-local exclusive scan
__device__ int g_bsum[NB_SCAN];       // per-block sums
__device__ int g_boff[NB_SCAN];       // scanned block offsets
__device__ int g_ptr[N_NODES + 1];    // CSR row pointers (by dst)
__device__ int g_pos[N_NODES];        // scatter cursors
__device__ int g_csr[N_EDGES];        // src ids grouped by dst

// ---------------------------------------------------------------- f32x2 helpers
__device__ __forceinline__ unsigned long long pk2(float lo, float hi) {
    unsigned long long r;
    asm("mov.b64 %0, {%1, %2};" : "=l"(r) : "f"(lo), "f"(hi));
    return r;
}
__device__ __forceinline__ void fma2(unsigned long long& d,
                                     unsigned long long a, unsigned long long b) {
    asm("fma.rn.f32x2 %0, %1, %2, %0;" : "+l"(d) : "l"(a), "l"(b));
}
__device__ __forceinline__ float sum2(unsigned long long v) {
    float lo, hi;
    asm("mov.b64 {%0, %1}, %2;" : "=f"(lo), "=f"(hi) : "l"(v));
    return lo + hi;
}

// ---------------------------------------------------------------- CSR build
__global__ void zero_deg_kernel() {
    int i = blockIdx.x * blockDim.x + threadIdx.x;
    if (i < N_NODES) g_deg[i] = 0;
}

__global__ void hist_kernel(const int* __restrict__ ei) {
    int e = blockIdx.x * blockDim.x + threadIdx.x;
    if (e >= N_EDGES) return;
    atomicAdd(&g_deg[__ldg(ei + N_EDGES + e)], 1);
}

// warp-shuffle block scan (1024 threads): local exclusive + block sum
__global__ void scan_block_kernel() {
    __shared__ int wsum[32];
    int t = threadIdx.x;
    int i = blockIdx.x * 1024 + t;
    int v = (i < N_NODES) ? g_deg[i] : 0;
    int lane = t & 31, w = t >> 5;

    int incl = v;
    #pragma unroll
    for (int o = 1; o < 32; o <<= 1) {
        int u = __shfl_up_sync(0xFFFFFFFFu, incl, o);
        if (lane >= o) incl += u;
    }
    if (lane == 31) wsum[w] = incl;
    __syncthreads();
    if (w == 0) {
        int s = wsum[lane];
        #pragma unroll
        for (int o = 1; o < 32; o <<= 1) {
            int u = __shfl_up_sync(0xFFFFFFFFu, s, o);
            if (lane >= o) s += u;
        }
        wsum[lane] = s;
    }
    __syncthreads();
    int off = (w > 0) ? wsum[w - 1] : 0;
    incl += off;
    if (i < N_NODES) g_excl[i] = incl - v;
    if (t == 1023) g_bsum[blockIdx.x] = incl;
}

// warp-shuffle scan of the 98 block sums (1 block, 128 threads)
__global__ void scan_bsum_kernel() {
    __shared__ int wsum[4];
    int t = threadIdx.x;
    int v = (t < NB_SCAN) ? g_bsum[t] : 0;
    int lane = t & 31, w = t >> 5;

    int incl = v;
    #pragma unroll
    for (int o = 1; o < 32; o <<= 1) {
        int u = __shfl_up_sync(0xFFFFFFFFu, incl, o);
        if (lane >= o) incl += u;
    }
    if (lane == 31) wsum[w] = incl;
    __syncthreads();
    if (t == 0) {
        int a = wsum[0];
        wsum[1] += a; a = wsum[1];
        wsum[2] += a; a = wsum[2];
        wsum[3] += a;
    }
    __syncthreads();
    int off = (w > 0) ? wsum[w - 1] : 0;
    incl += off;
    if (t < NB_SCAN) g_boff[t] = incl - v;
    if (t == 127) g_ptr[N_NODES] = incl;   // == N_EDGES
}

__global__ void finalize_ptr_kernel() {
    int i = blockIdx.x * blockDim.x + threadIdx.x;
    if (i >= N_NODES) return;
    int p = g_excl[i] + g_boff[i >> 10];
    g_ptr[i] = p;
    g_pos[i] = p;
}

__global__ void scatter_kernel(const int* __restrict__ ei) {
    int e = blockIdx.x * blockDim.x + threadIdx.x;
    if (e >= N_EDGES) return;
    int s = __ldg(ei + e);
    int d = __ldg(ei + N_EDGES + e);
    int p = atomicAdd(&g_pos[d], 1);
    g_csr[p] = s;
}

// ---------------------------------------------------------------- GEMM1 (FFMA2, K-paired)
// Epilogue: l-part (cols 0..63) -> bf16 table g_y1l; r-part -> fp32 g_y1r.
__global__ void gemm1_kernel(const float* __restrict__ x,
                             const float* __restrict__ Wl,
                             const float* __restrict__ Wr) {
    __shared__ float As[64][128];  // 32 KB
    const int bm = blockIdx.x * 64;
    const int t  = threadIdx.x;

    for (int i = t; i < 64 * 32; i += 256) {
        int m = i >> 5, k4 = i & 31;
        int gm = bm + m;
        float4 v = make_float4(0.f, 0.f, 0.f, 0.f);
        if (gm < N_NODES) v = __ldg((const float4*)x + gm * 32 + k4);
        *(float4*)&As[m][k4 * 4] = v;
    }
    __syncthreads();

    const int ng = t & 31, mg = t >> 5;
    const int n0 = ng * 4, m0 = mg * 8;
    const bool is_l = (n0 < 64);
    const float* B = is_l ? (Wl + n0) : (Wr + (n0 - 64));

    unsigned long long acc[8][4];
    #pragma unroll
    for (int i = 0; i < 8; i++)
        { acc[i][0] = 0ull; acc[i][1] = 0ull; acc[i][2] = 0ull; acc[i][3] = 0ull; }

    #pragma unroll 4
    for (int k = 0; k < 128; k += 2) {
        float4 b0 = __ldg((const float4*)(B + k * 64));
        float4 b1 = __ldg((const float4*)(B + (k + 1) * 64));
        unsigned long long bx = pk2(b0.x, b1.x);
        unsigned long long by = pk2(b0.y, b1.y);
        unsigned long long bz = pk2(b0.z, b1.z);
        unsigned long long bw = pk2(b0.w, b1.w);
        #pragma unroll
        for (int i = 0; i < 8; i++) {
            float2 a = *(const float2*)&As[m0 + i][k];
            unsigned long long ap = pk2(a.x, a.y);
            fma2(acc[i][0], ap, bx);
            fma2(acc[i][1], ap, by);
            fma2(acc[i][2], ap, bz);
            fma2(acc[i][3], ap, bw);
        }
    }

    #pragma unroll
    for (int i = 0; i < 8; i++) {
        int gm = bm + m0 + i;
        if (gm >= N_NODES) continue;
        float r0 = sum2(acc[i][0]), r1 = sum2(acc[i][1]);
        float r2 = sum2(acc[i][2]), r3 = sum2(acc[i][3]);
        if (is_l) {
            __nv_bfloat162 p0 = __float22bfloat162_rn(make_float2(r0, r1));
            __nv_bfloat162 p1 = __float22bfloat162_rn(make_float2(r2, r3));
            uint2 u;
            u.x = *(unsigned*)&p0;
            u.y = *(unsigned*)&p1;
            *(uint2*)(g_y1l + gm * 64 + n0) = u;
        } else {
            *(float4*)&g_y1r[gm * 64 + (n0 - 64)] = make_float4(r0, r1, r2, r3);
        }
    }
}

// ---------------------------------------------------------------- agg1 (fused mean-agg + self + bias + relu)
// 16 threads per node (2 nodes/warp); thread j owns 4 bf16 (8B) of the 64-f
// l-part row (128 B/row). Accumulation in fp32.
__global__ void agg1_kernel(const float* __restrict__ b1) {
    int g = (blockIdx.x * blockDim.x + threadIdx.x) >> 4;
    int j = threadIdx.x & 15;
    if (g >= N_NODES) return;

    int beg = __ldg(&g_ptr[g]), end = __ldg(&g_ptr[g + 1]);
    float4 acc = make_float4(0.f, 0.f, 0.f, 0.f);

    int k = beg;
    for (; k + 4 <= end; k += 4) {
        int s0 = __ldg(&g_csr[k]);
        int s1 = __ldg(&g_csr[k + 1]);
        int s2 = __ldg(&g_csr[k + 2]);
        int s3 = __ldg(&g_csr[k + 3]);
        uint2 u0 = __ldg((const uint2*)(g_y1l + s0 * 64) + j);
        uint2 u1 = __ldg((const uint2*)(g_y1l + s1 * 64) + j);
        uint2 u2 = __ldg((const uint2*)(g_y1l + s2 * 64) + j);
        uint2 u3 = __ldg((const uint2*)(g_y1l + s3 * 64) + j);
        float2 a0 = __bfloat1622float2(*(__nv_bfloat162*)&u0.x);
        float2 b0 = __bfloat1622float2(*(__nv_bfloat162*)&u0.y);
        float2 a1 = __bfloat1622float2(*(__nv_bfloat162*)&u1.x);
        float2 b1v = __bfloat1622float2(*(__nv_bfloat162*)&u1.y);
        float2 a2 = __bfloat1622float2(*(__nv_bfloat162*)&u2.x);
        float2 b2v = __bfloat1622float2(*(__nv_bfloat162*)&u2.y);
        float2 a3 = __bfloat1622float2(*(__nv_bfloat162*)&u3.x);
        float2 b3v = __bfloat1622float2(*(__nv_bfloat162*)&u3.y);
        acc.x += a0.x + a1.x + a2.x + a3.x;
        acc.y += a0.y + a1.y + a2.y + a3.y;
        acc.z += b0.x + b1v.x + b2v.x + b3v.x;
        acc.w += b0.y + b1v.y + b2v.y + b3v.y;
    }
    for (; k < end; k++) {
        int s = __ldg(&g_csr[k]);
        uint2 u = __ldg((const uint2*)(g_y1l + s * 64) + j);
        float2 a = __bfloat1622float2(*(__nv_bfloat162*)&u.x);
        float2 b = __bfloat1622float2(*(__nv_bfloat162*)&u.y);
        acc.x += a.x; acc.y += a.y; acc.z += b.x; acc.w += b.y;
    }

    float inv = 1.0f / fmaxf((float)(end - beg), 1.0f);
    float4 self = __ldg((const float4*)g_y1r + g * 16 + j);
    float4 bb   = __ldg((const float4*)b1 + j);
    float4 h;
    h.x = fmaxf(acc.x * inv + self.x + bb.x, 0.f);
    h.y = fmaxf(acc.y * inv + self.y + bb.y, 0.f);
    h.z = fmaxf(acc.z * inv + self.z + bb.z, 0.f);
    h.w = fmaxf(acc.w * inv + self.w + bb.w, 0.f);
    *((float4*)g_h + g * 16 + j) = h;
}

// ---------------------------------------------------------------- GEMM2 (FFMA2, K-paired)
__global__ void gemm2_kernel(const float* __restrict__ Wl,
                             const float* __restrict__ Wr) {
    __shared__ float As[64][64];  // 16 KB
    const int bm = blockIdx.x * 64;
    const int t  = threadIdx.x;

    for (int i = t; i < 64 * 16; i += 160) {
        int m = i >> 4, k4 = i & 15;
        int gm = bm + m;
        float4 v = make_float4(0.f, 0.f, 0.f, 0.f);
        if (gm < N_NODES) v = *((const float4*)g_h + gm * 16 + k4);
        *(float4*)&As[m][k4 * 4] = v;
    }
    __syncthreads();

    const int ng = t % 20, mg = t / 20;
    const int n0 = ng * 4, m0 = mg * 8;
    const float* B = (n0 < 40) ? (Wl + n0) : (Wr + (n0 - 40));

    unsigned long long acc[8][4];
    #pragma unroll
    for (int i = 0; i < 8; i++)
        { acc[i][0] = 0ull; acc[i][1] = 0ull; acc[i][2] = 0ull; acc[i][3] = 0ull; }

    #pragma unroll 4
    for (int k = 0; k < 64; k += 2) {
        float4 b0 = __ldg((const float4*)(B + k * 40));
        float4 b1 = __ldg((const float4*)(B + (k + 1) * 40));
        unsigned long long bx = pk2(b0.x, b1.x);
        unsigned long long by = pk2(b0.y, b1.y);
        unsigned long long bz = pk2(b0.z, b1.z);
        unsigned long long bw = pk2(b0.w, b1.w);
        #pragma unroll
        for (int i = 0; i < 8; i++) {
            float2 a = *(const float2*)&As[m0 + i][k];
            unsigned long long ap = pk2(a.x, a.y);
            fma2(acc[i][0], ap, bx);
            fma2(acc[i][1], ap, by);
            fma2(acc[i][2], ap, bz);
            fma2(acc[i][3], ap, bw);
        }
    }

    #pragma unroll
    for (int i = 0; i < 8; i++) {
        int gm = bm + m0 + i;
        if (gm < N_NODES)
            *(float4*)&g_y2[gm * 80 + n0] =
                make_float4(sum2(acc[i][0]), sum2(acc[i][1]),
                            sum2(acc[i][2]), sum2(acc[i][3]));
    }
}

// ---------------------------------------------------------------- agg2 + log_softmax (fused)
// 2 nodes per warp (16-lane halves); sublanes 0..9 own the 10 float4 chunks
// of the 40-f z-part. Reductions via width-16 shuffles.
__global__ void agg2_kernel(const float* __restrict__ b2, float* __restrict__ out) {
    int gw   = (blockIdx.x * blockDim.x + threadIdx.x) >> 5;   // warp id
    int lane = threadIdx.x & 31;
    int half = lane >> 4;          // which node in the pair
    int sl   = lane & 15;          // sublane within the 16-lane group
    int n = gw * 2 + half;
    if (n >= N_NODES) return;

    int beg = __ldg(&g_ptr[n]), end = __ldg(&g_ptr[n + 1]);
    bool act = sl < 10;
    float4 acc = make_float4(0.f, 0.f, 0.f, 0.f);

    int k = beg;
    for (; k + 4 <= end; k += 4) {
        int s0 = __ldg(&g_csr[k]);
        int s1 = __ldg(&g_csr[k + 1]);
        int s2 = __ldg(&g_csr[k + 2]);
        int s3 = __ldg(&g_csr[k + 3]);
        if (act) {
            float4 v0 = __ldg((const float4*)g_y2 + s0 * 20 + sl);
            float4 v1 = __ldg((const float4*)g_y2 + s1 * 20 + sl);
            float4 v2 = __ldg((const float4*)g_y2 + s2 * 20 + sl);
            float4 v3 = __ldg((const float4*)g_y2 + s3 * 20 + sl);
            acc.x += v0.x + v1.x + v2.x + v3.x;
            acc.y += v0.y + v1.y + v2.y + v3.y;
            acc.z += v0.z + v1.z + v2.z + v3.z;
            acc.w += v0.w + v1.w + v2.w + v3.w;
        }
    }
    for (; k < end; k++) {
        int s = __ldg(&g_csr[k]);
        if (act) {
            float4 v = __ldg((const float4*)g_y2 + s * 20 + sl);
            acc.x += v.x; acc.y += v.y; acc.z += v.z; acc.w += v.w;
        }
    }

    float inv = 1.0f / fmaxf((float)(end - beg), 1.0f);
    float4 v = make_float4(-3.0e38f, -3.0e38f, -3.0e38f, -3.0e38f);
    if (act) {
        float4 self = __ldg((const float4*)g_y2 + n * 20 + 10 + sl);
        float4 bb   = __ldg((const float4*)b2 + sl);
        v.x = acc.x * inv + self.x + bb.x;
        v.y = acc.y * inv + self.y + bb.y;
        v.z = acc.z * inv + self.z + bb.z;
        v.w = acc.w * inv + self.w + bb.w;
    }

    float m = fmaxf(fmaxf(v.x, v.y), fmaxf(v.z, v.w));
    #pragma unroll
    for (int o = 8; o; o >>= 1) m = fmaxf(m, __shfl_xor_sync(0xFFFFFFFFu, m, o, 16));

    float s = act ? (expf(v.x - m) + expf(v.y - m) + expf(v.z - m) + expf(v.w - m)) : 0.f;
    #pragma unroll
    for (int o = 8; o; o >>= 1) s += __shfl_xor_sync(0xFFFFFFFFu, s, o, 16);

    float lse = m + logf(s);
    if (act)
        *((float4*)out + n * 10 + sl) =
            make_float4(v.x - lse, v.y - lse, v.z - lse, v.w - lse);
}

// ---------------------------------------------------------------- launch
// Captured graph: main stream runs gemm1 concurrently with the CSR chain on a
// side stream; join; agg1; gemm2; agg2.
extern "C" void kernel_launch(void* const* d_in, const int* in_sizes, int n_in,
                              void* d_out, int out_size) {
    const float* x   = 0; const int* ei = 0;
    const float* W1l = 0; const float* W1r = 0; const float* b1 = 0;
    const float* W2l = 0; const float* W2r = 0; const float* b2 = 0;

    for (int i = 0; i < n_in; i++) {
        int sz = in_sizes[i];
        const void* p = d_in[i];
        if      (sz == N_NODES * 128)  x  = (const float*)p;
        else if (sz == 2 * N_EDGES)    ei = (const int*)p;
        else if (sz == 128 * 64) { if (!W1l) W1l = (const float*)p; else W1r = (const float*)p; }
        else if (sz == 64 * 40)  { if (!W2l) W2l = (const float*)p; else W2r = (const float*)p; }
        else if (sz == 64)             b1 = (const float*)p;
        else if (sz == 40)             b2 = (const float*)p;
    }
    float* out = (float*)d_out;

    cudaStream_t s1;
    cudaEvent_t evFork, evJoin;
    cudaStreamCreateWithFlags(&s1, cudaStreamNonBlocking);
    cudaEventCreateWithFlags(&evFork, cudaEventDisableTiming);
    cudaEventCreateWithFlags(&evJoin, cudaEventDisableTiming);

    cudaEventRecord(evFork, 0);
    cudaStreamWaitEvent(s1, evFork, 0);

    // side stream: CSR build
    zero_deg_kernel    <<<(N_NODES + 255) / 256, 256, 0, s1>>>();
    hist_kernel        <<<(N_EDGES + 255) / 256, 256, 0, s1>>>(ei);
    scan_block_kernel  <<<NB_SCAN, 1024, 0, s1>>>();
    scan_bsum_kernel   <<<1, 128, 0, s1>>>();
    finalize_ptr_kernel<<<(N_NODES + 255) / 256, 256, 0, s1>>>();
    scatter_kernel     <<<(N_EDGES + 255) / 256, 256, 0, s1>>>(ei);
    cudaEventRecord(evJoin, s1);

    // main stream: gemm1 runs concurrently with the CSR chain
    gemm1_kernel<<<(N_NODES + 63) / 64, 256>>>(x, W1l, W1r);

    // join, then the dependent tail
    cudaStreamWaitEvent(0, evJoin, 0);
    agg1_kernel <<<(N_NODES * 16 + 255) / 256, 256>>>(b1);
    gemm2_kernel<<<(N_NODES + 63) / 64, 160>>>(W2l, W2r);
    agg2_kernel <<<(N_NODES / 2 * 32 + 255) / 256, 256>>>(b2, out);
}

// round 14
// speedup vs baseline: 1.4355x; 1.4355x over previous
#include <cuda_runtime.h>

#define N_NODES 100000
#define N_EDGES 1600000
#define NB_SCAN 98            // ceil(100000/1024)
// layer dims: F_IN=128, HID=64, N_CLS=40

// Scratch (device globals: allocation-free, graph-safe)
__device__ __align__(16) float g_y1[N_NODES * 128];   // [x@W1_l | x@W1_r]
__device__ __align__(16) float g_h[N_NODES * 64];     // relu output
__device__ __align__(16) float g_y2[N_NODES * 80];    // [h@W2_l | h@W2_r]
__device__ int g_deg[N_NODES];        // in-degree histogram
__device__ int g_excl[N_NODES];       // block-local exclusive scan
__device__ int g_bsum[NB_SCAN];       // per-block sums
__device__ int g_boff[NB_SCAN];       // scanned block offsets
__device__ int g_ptr[N_NODES + 1];    // CSR row pointers (by dst)
__device__ int g_pos[N_NODES];        // scatter cursors
__device__ __align__(16) int g_csr[N_EDGES];   // src ids grouped by dst (16B-aligned for int4)

// ---------------------------------------------------------------- f32x2 helpers
__device__ __forceinline__ unsigned long long pk2(float lo, float hi) {
    unsigned long long r;
    asm("mov.b64 %0, {%1, %2};" : "=l"(r) : "f"(lo), "f"(hi));
    return r;
}
__device__ __forceinline__ void fma2(unsigned long long& d,
                                     unsigned long long a, unsigned long long b) {
    asm("fma.rn.f32x2 %0, %1, %2, %0;" : "+l"(d) : "l"(a), "l"(b));
}
__device__ __forceinline__ float sum2(unsigned long long v) {
    float lo, hi;
    asm("mov.b64 {%0, %1}, %2;" : "=f"(lo), "=f"(hi) : "l"(v));
    return lo + hi;
}

// ---------------------------------------------------------------- CSR build
__global__ void zero_deg_kernel() {
    int i = blockIdx.x * blockDim.x + threadIdx.x;
    if (i < N_NODES) g_deg[i] = 0;
}

__global__ void hist_kernel(const int* __restrict__ ei) {
    int e = blockIdx.x * blockDim.x + threadIdx.x;
    if (e >= N_EDGES) return;
    atomicAdd(&g_deg[__ldg(ei + N_EDGES + e)], 1);
}

// warp-shuffle block scan (1024 threads): local exclusive + block sum
__global__ void scan_block_kernel() {
    __shared__ int wsum[32];
    int t = threadIdx.x;
    int i = blockIdx.x * 1024 + t;
    int v = (i < N_NODES) ? g_deg[i] : 0;
    int lane = t & 31, w = t >> 5;

    int incl = v;
    #pragma unroll
    for (int o = 1; o < 32; o <<= 1) {
        int u = __shfl_up_sync(0xFFFFFFFFu, incl, o);
        if (lane >= o) incl += u;
    }
    if (lane == 31) wsum[w] = incl;
    __syncthreads();
    if (w == 0) {
        int s = wsum[lane];
        #pragma unroll
        for (int o = 1; o < 32; o <<= 1) {
            int u = __shfl_up_sync(0xFFFFFFFFu, s, o);
            if (lane >= o) s += u;
        }
        wsum[lane] = s;
    }
    __syncthreads();
    int off = (w > 0) ? wsum[w - 1] : 0;
    incl += off;
    if (i < N_NODES) g_excl[i] = incl - v;
    if (t == 1023) g_bsum[blockIdx.x] = incl;
}

// warp-shuffle scan of the 98 block sums (1 block, 128 threads)
__global__ void scan_bsum_kernel() {
    __shared__ int wsum[4];
    int t = threadIdx.x;
    int v = (t < NB_SCAN) ? g_bsum[t] : 0;
    int lane = t & 31, w = t >> 5;

    int incl = v;
    #pragma unroll
    for (int o = 1; o < 32; o <<= 1) {
        int u = __shfl_up_sync(0xFFFFFFFFu, incl, o);
        if (lane >= o) incl += u;
    }
    if (lane == 31) wsum[w] = incl;
    __syncthreads();
    if (t == 0) {
        int a = wsum[0];
        wsum[1] += a; a = wsum[1];
        wsum[2] += a; a = wsum[2];
        wsum[3] += a;
    }
    __syncthreads();
    int off = (w > 0) ? wsum[w - 1] : 0;
    incl += off;
    if (t < NB_SCAN) g_boff[t] = incl - v;
    if (t == 127) g_ptr[N_NODES] = incl;   // == N_EDGES
}

__global__ void finalize_ptr_kernel() {
    int i = blockIdx.x * blockDim.x + threadIdx.x;
    if (i >= N_NODES) return;
    int p = g_excl[i] + g_boff[i >> 10];
    g_ptr[i] = p;
    g_pos[i] = p;
}

__global__ void scatter_kernel(const int* __restrict__ ei) {
    int e = blockIdx.x * blockDim.x + threadIdx.x;
    if (e >= N_EDGES) return;
    int s = __ldg(ei + e);
    int d = __ldg(ei + N_EDGES + e);
    int p = atomicAdd(&g_pos[d], 1);
    g_csr[p] = s;
}

// ---------------------------------------------------------------- GEMM1 (FFMA2, K-paired)
__global__ void gemm1_kernel(const float* __restrict__ x,
                             const float* __restrict__ Wl,
                             const float* __restrict__ Wr) {
    __shared__ float As[64][128];  // 32 KB
    const int bm = blockIdx.x * 64;
    const int t  = threadIdx.x;

    for (int i = t; i < 64 * 32; i += 256) {
        int m = i >> 5, k4 = i & 31;
        int gm = bm + m;
        float4 v = make_float4(0.f, 0.f, 0.f, 0.f);
        if (gm < N_NODES) v = __ldg((const float4*)x + gm * 32 + k4);
        *(float4*)&As[m][k4 * 4] = v;
    }
    __syncthreads();

    const int ng = t & 31, mg = t >> 5;
    const int n0 = ng * 4, m0 = mg * 8;
    const float* B = (n0 < 64) ? (Wl + n0) : (Wr + (n0 - 64));

    unsigned long long acc[8][4];
    #pragma unroll
    for (int i = 0; i < 8; i++)
        { acc[i][0] = 0ull; acc[i][1] = 0ull; acc[i][2] = 0ull; acc[i][3] = 0ull; }

    #pragma unroll 4
    for (int k = 0; k < 128; k += 2) {
        float4 b0 = __ldg((const float4*)(B + k * 64));
        float4 b1 = __ldg((const float4*)(B + (k + 1) * 64));
        unsigned long long bx = pk2(b0.x, b1.x);
        unsigned long long by = pk2(b0.y, b1.y);
        unsigned long long bz = pk2(b0.z, b1.z);
        unsigned long long bw = pk2(b0.w, b1.w);
        #pragma unroll
        for (int i = 0; i < 8; i++) {
            float2 a = *(const float2*)&As[m0 + i][k];
            unsigned long long ap = pk2(a.x, a.y);
            fma2(acc[i][0], ap, bx);
            fma2(acc[i][1], ap, by);
            fma2(acc[i][2], ap, bz);
            fma2(acc[i][3], ap, bw);
        }
    }

    #pragma unroll
    for (int i = 0; i < 8; i++) {
        int gm = bm + m0 + i;
        if (gm < N_NODES)
            *(float4*)&g_y1[gm * 128 + n0] =
                make_float4(sum2(acc[i][0]), sum2(acc[i][1]),
                            sum2(acc[i][2]), sum2(acc[i][3]));
    }
}

// ---------------------------------------------------------------- agg1 (fused mean-agg + self + bias + relu)
// 16 threads per node (2 nodes/warp); thread j owns float4 chunk j of the
// 64-f l-part. Indices loaded 4-at-a-time via int4 after alignment.
__global__ void agg1_kernel(const float* __restrict__ b1) {
    int g = (blockIdx.x * blockDim.x + threadIdx.x) >> 4;
    int j = threadIdx.x & 15;
    if (g >= N_NODES) return;

    int beg = __ldg(&g_ptr[g]), end = __ldg(&g_ptr[g + 1]);
    float4 acc = make_float4(0.f, 0.f, 0.f, 0.f);

    int k = beg;
    // align k to 4 for int4 index loads
    for (; k < end && (k & 3); k++) {
        int s = __ldg(&g_csr[k]);
        float4 v = __ldg((const float4*)g_y1 + s * 32 + j);
        acc.x += v.x; acc.y += v.y; acc.z += v.z; acc.w += v.w;
    }
    for (; k + 4 <= end; k += 4) {
        int4 s4 = *(const int4*)(g_csr + k);    // 1 LDG.128 replaces 4 scalar index loads
        float4 v0 = __ldg((const float4*)g_y1 + s4.x * 32 + j);
        float4 v1 = __ldg((const float4*)g_y1 + s4.y * 32 + j);
        float4 v2 = __ldg((const float4*)g_y1 + s4.z * 32 + j);
        float4 v3 = __ldg((const float4*)g_y1 + s4.w * 32 + j);
        acc.x += v0.x + v1.x + v2.x + v3.x;
        acc.y += v0.y + v1.y + v2.y + v3.y;
        acc.z += v0.z + v1.z + v2.z + v3.z;
        acc.w += v0.w + v1.w + v2.w + v3.w;
    }
    for (; k < end; k++) {
        int s = __ldg(&g_csr[k]);
        float4 v = __ldg((const float4*)g_y1 + s * 32 + j);
        acc.x += v.x; acc.y += v.y; acc.z += v.z; acc.w += v.w;
    }

    float inv = 1.0f / fmaxf((float)(end - beg), 1.0f);
    float4 self = __ldg((const float4*)g_y1 + g * 32 + 16 + j);
    float4 bb   = __ldg((const float4*)b1 + j);
    float4 h;
    h.x = fmaxf(acc.x * inv + self.x + bb.x, 0.f);
    h.y = fmaxf(acc.y * inv + self.y + bb.y, 0.f);
    h.z = fmaxf(acc.z * inv + self.z + bb.z, 0.f);
    h.w = fmaxf(acc.w * inv + self.w + bb.w, 0.f);
    *((float4*)g_h + g * 16 + j) = h;
}

// ---------------------------------------------------------------- GEMM2 (FFMA2, K-paired)
__global__ void gemm2_kernel(const float* __restrict__ Wl,
                             const float* __restrict__ Wr) {
    __shared__ float As[64][64];  // 16 KB
    const int bm = blockIdx.x * 64;
    const int t  = threadIdx.x;

    for (int i = t; i < 64 * 16; i += 160) {
        int m = i >> 4, k4 = i & 15;
        int gm = bm + m;
        float4 v = make_float4(0.f, 0.f, 0.f, 0.f);
        if (gm < N_NODES) v = *((const float4*)g_h + gm * 16 + k4);
        *(float4*)&As[m][k4 * 4] = v;
    }
    __syncthreads();

    const int ng = t % 20, mg = t / 20;
    const int n0 = ng * 4, m0 = mg * 8;
    const float* B = (n0 < 40) ? (Wl + n0) : (Wr + (n0 - 40));

    unsigned long long acc[8][4];
    #pragma unroll
    for (int i = 0; i < 8; i++)
        { acc[i][0] = 0ull; acc[i][1] = 0ull; acc[i][2] = 0ull; acc[i][3] = 0ull; }

    #pragma unroll 4
    for (int k = 0; k < 64; k += 2) {
        float4 b0 = __ldg((const float4*)(B + k * 40));
        float4 b1 = __ldg((const float4*)(B + (k + 1) * 40));
        unsigned long long bx = pk2(b0.x, b1.x);
        unsigned long long by = pk2(b0.y, b1.y);
        unsigned long long bz = pk2(b0.z, b1.z);
        unsigned long long bw = pk2(b0.w, b1.w);
        #pragma unroll
        for (int i = 0; i < 8; i++) {
            float2 a = *(const float2*)&As[m0 + i][k];
            unsigned long long ap = pk2(a.x, a.y);
            fma2(acc[i][0], ap, bx);
            fma2(acc[i][1], ap, by);
            fma2(acc[i][2], ap, bz);
            fma2(acc[i][3], ap, bw);
        }
    }

    #pragma unroll
    for (int i = 0; i < 8; i++) {
        int gm = bm + m0 + i;
        if (gm < N_NODES)
            *(float4*)&g_y2[gm * 80 + n0] =
                make_float4(sum2(acc[i][0]), sum2(acc[i][1]),
                            sum2(acc[i][2]), sum2(acc[i][3]));
    }
}

// ---------------------------------------------------------------- agg2 + log_softmax (fused)
// 2 nodes per warp (16-lane halves); sublanes 0..9 own the 10 float4 chunks
// of the 40-f z-part. int4 index loads; width-16 shuffle reductions.
__global__ void agg2_kernel(const float* __restrict__ b2, float* __restrict__ out) {
    int gw   = (blockIdx.x * blockDim.x + threadIdx.x) >> 5;   // warp id
    int lane = threadIdx.x & 31;
    int half = lane >> 4;          // which node in the pair
    int sl   = lane & 15;          // sublane within the 16-lane group
    int n = gw * 2 + half;
    if (n >= N_NODES) return;

    int beg = __ldg(&g_ptr[n]), end = __ldg(&g_ptr[n + 1]);
    bool act = sl < 10;
    float4 acc = make_float4(0.f, 0.f, 0.f, 0.f);

    int k = beg;
    for (; k < end && (k & 3); k++) {
        int s = __ldg(&g_csr[k]);
        if (act) {
            float4 v = __ldg((const float4*)g_y2 + s * 20 + sl);
            acc.x += v.x; acc.y += v.y; acc.z += v.z; acc.w += v.w;
        }
    }
    for (; k + 4 <= end; k += 4) {
        int4 s4 = *(const int4*)(g_csr + k);
        if (act) {
            float4 v0 = __ldg((const float4*)g_y2 + s4.x * 20 + sl);
            float4 v1 = __ldg((const float4*)g_y2 + s4.y * 20 + sl);
            float4 v2 = __ldg((const float4*)g_y2 + s4.z * 20 + sl);
            float4 v3 = __ldg((const float4*)g_y2 + s4.w * 20 + sl);
            acc.x += v0.x + v1.x + v2.x + v3.x;
            acc.y += v0.y + v1.y + v2.y + v3.y;
            acc.z += v0.z + v1.z + v2.z + v3.z;
            acc.w += v0.w + v1.w + v2.w + v3.w;
        }
    }
    for (; k < end; k++) {
        int s = __ldg(&g_csr[k]);
        if (act) {
            float4 v = __ldg((const float4*)g_y2 + s * 20 + sl);
            acc.x += v.x; acc.y += v.y; acc.z += v.z; acc.w += v.w;
        }
    }

    float inv = 1.0f / fmaxf((float)(end - beg), 1.0f);
    float4 v = make_float4(-3.0e38f, -3.0e38f, -3.0e38f, -3.0e38f);
    if (act) {
        float4 self = __ldg((const float4*)g_y2 + n * 20 + 10 + sl);
        float4 bb   = __ldg((const float4*)b2 + sl);
        v.x = acc.x * inv + self.x + bb.x;
        v.y = acc.y * inv + self.y + bb.y;
        v.z = acc.z * inv + self.z + bb.z;
        v.w = acc.w * inv + self.w + bb.w;
    }

    float m = fmaxf(fmaxf(v.x, v.y), fmaxf(v.z, v.w));
    #pragma unroll
    for (int o = 8; o; o >>= 1) m = fmaxf(m, __shfl_xor_sync(0xFFFFFFFFu, m, o, 16));

    float s = act ? (expf(v.x - m) + expf(v.y - m) + expf(v.z - m) + expf(v.w - m)) : 0.f;
    #pragma unroll
    for (int o = 8; o; o >>= 1) s += __shfl_xor_sync(0xFFFFFFFFu, s, o, 16);

    float lse = m + logf(s);
    if (act)
        *((float4*)out + n * 10 + sl) =
            make_float4(v.x - lse, v.y - lse, v.z - lse, v.w - lse);
}

// ---------------------------------------------------------------- launch
// Captured graph: main stream runs gemm1 concurrently with the CSR chain on a
// side stream; join; agg1; gemm2; agg2.
extern "C" void kernel_launch(void* const* d_in, const int* in_sizes, int n_in,
                              void* d_out, int out_size) {
    const float* x   = 0; const int* ei = 0;
    const float* W1l = 0; const float* W1r = 0; const float* b1 = 0;
    const float* W2l = 0; const float* W2r = 0; const float* b2 = 0;

    for (int i = 0; i < n_in; i++) {
        int sz = in_sizes[i];
        const void* p = d_in[i];
        if      (sz == N_NODES * 128)  x  = (const float*)p;
        else if (sz == 2 * N_EDGES)    ei = (const int*)p;
        else if (sz == 128 * 64) { if (!W1l) W1l = (const float*)p; else W1r = (const float*)p; }
        else if (sz == 64 * 40)  { if (!W2l) W2l = (const float*)p; else W2r = (const float*)p; }
        else if (sz == 64)             b1 = (const float*)p;
        else if (sz == 40)             b2 = (const float*)p;
    }
    float* out = (float*)d_out;

    cudaStream_t s1;
    cudaEvent_t evFork, evJoin;
    cudaStreamCreateWithFlags(&s1, cudaStreamNonBlocking);
    cudaEventCreateWithFlags(&evFork, cudaEventDisableTiming);
    cudaEventCreateWithFlags(&evJoin, cudaEventDisableTiming);

    cudaEventRecord(evFork, 0);
    cudaStreamWaitEvent(s1, evFork, 0);

    // side stream: CSR build
    zero_deg_kernel    <<<(N_NODES + 255) / 256, 256, 0, s1>>>();
    hist_kernel        <<<(N_EDGES + 255) / 256, 256, 0, s1>>>(ei);
    scan_block_kernel  <<<NB_SCAN, 1024, 0, s1>>>();
    scan_bsum_kernel   <<<1, 128, 0, s1>>>();
    finalize_ptr_kernel<<<(N_NODES + 255) / 256, 256, 0, s1>>>();
    scatter_kernel     <<<(N_EDGES + 255) / 256, 256, 0, s1>>>(ei);
    cudaEventRecord(evJoin, s1);

    // main stream: gemm1 runs concurrently with the CSR chain
    gemm1_kernel<<<(N_NODES + 63) / 64, 256>>>(x, W1l, W1r);

    // join, then the dependent tail
    cudaStreamWaitEvent(0, evJoin, 0);
    agg1_kernel <<<(N_NODES * 16 + 255) / 256, 256>>>(b1);
    gemm2_kernel<<<(N_NODES + 63) / 64, 160>>>(W2l, W2r);
    agg2_kernel <<<(N_NODES / 2 * 32 + 255) / 256, 256>>>(b2, out);
}